// round 1
// baseline (speedup 1.0000x reference)
#include <cuda_runtime.h>
#include <math.h>

#define Bq 16
#define Nq 512
#define Dq 768
#define Hq 12
#define DKq 64
#define NDq 32
#define TOK (Bq*Nq)   // 8192

// Scratch (static __device__ arrays: no allocation)
__device__ float g_x[TOK*Dq];   // layernormed features
__device__ float g_q[TOK*Dq];   // (B,N,H,DK)
__device__ float g_k[TOK*Dq];
__device__ float g_v[TOK*Dq];
__device__ float g_o[TOK*Dq];   // attention output pre-proj (B,N,H,DK)
__device__ float g_px[TOK];
__device__ float g_py[TOK];
__device__ int   g_btab[201];   // d2 -> bin = int(2*sqrt(d2))

// ---------------------------------------------------------------------------
// LayerNorm: one block per token, 256 threads, 3 elems/thread
// ---------------------------------------------------------------------------
__global__ void __launch_bounds__(256) ln_kernel(const float* __restrict__ f,
                                                 const float* __restrict__ gamma,
                                                 const float* __restrict__ beta) {
    int t = blockIdx.x;
    const float* in = f + (size_t)t * Dq;
    float* out = g_x + (size_t)t * Dq;
    int tid = threadIdx.x;
    float v0 = in[tid], v1 = in[tid + 256], v2 = in[tid + 512];

    __shared__ float red[8];
    __shared__ float bc;

    float s = v0 + v1 + v2;
    #pragma unroll
    for (int o = 16; o > 0; o >>= 1) s += __shfl_down_sync(0xffffffffu, s, o);
    if ((tid & 31) == 0) red[tid >> 5] = s;
    __syncthreads();
    if (tid == 0) {
        float tot = 0.f;
        #pragma unroll
        for (int i = 0; i < 8; i++) tot += red[i];
        bc = tot * (1.0f / 768.0f);
    }
    __syncthreads();
    float mean = bc;
    float d0 = v0 - mean, d1 = v1 - mean, d2 = v2 - mean;
    float ss = d0 * d0 + d1 * d1 + d2 * d2;
    #pragma unroll
    for (int o = 16; o > 0; o >>= 1) ss += __shfl_down_sync(0xffffffffu, ss, o);
    __syncthreads();                 // everyone done reading bc/red
    if ((tid & 31) == 0) red[tid >> 5] = ss;
    __syncthreads();
    if (tid == 0) {
        float tot = 0.f;
        #pragma unroll
        for (int i = 0; i < 8; i++) tot += red[i];
        bc = tot * (1.0f / 768.0f);
    }
    __syncthreads();
    float inv = rsqrtf(bc + 1e-5f);
    out[tid]       = d0 * inv * gamma[tid]       + beta[tid];
    out[tid + 256] = d1 * inv * gamma[tid + 256] + beta[tid + 256];
    out[tid + 512] = d2 * inv * gamma[tid + 512] + beta[tid + 512];
}

// ---------------------------------------------------------------------------
// Patch bins: one thread per token. Exact replication of reference float math.
// Also fills the dist-bin table (fp64 sqrt, immune to fast-math).
// ---------------------------------------------------------------------------
__global__ void __launch_bounds__(256) bins_kernel(const float* __restrict__ boxes,
                                                   const int* __restrict__ im) {
    int idx = blockIdx.x * blockDim.x + threadIdx.x;
    if (idx < 201) g_btab[idx] = (int)(2.0 * sqrt((double)idx));
    if (idx >= TOK) return;
    int b = idx / Nq;
    float wf = (float)im[b * 4 + 0];
    float hf = (float)im[b * 4 + 1];
    const float* bx = boxes + (size_t)idx * 4;
    float x1 = bx[0] * wf, y1 = bx[1] * hf, x2 = bx[2] * wf, y2 = bx[3] * hf;
    float spw = floorf(wf / 11.0f), sph = floorf(hf / 11.0f);
    float cx = floorf((x1 + x2) / 2.0f), cy = floorf((y1 + y2) / 2.0f);
    int px = 0, py = 0;
    #pragma unroll
    for (int i = 0; i < 11; i++) {
        float lo = (float)i * spw, hi = (float)(i + 1) * spw;
        if (lo <= cx && cx <= hi) { px = i; break; }
    }
    #pragma unroll
    for (int i = 0; i < 11; i++) {
        float lo = (float)i * sph, hi = (float)(i + 1) * sph;
        if (lo <= cy && cy <= hi) { py = i; break; }
    }
    g_px[idx] = (float)px;
    g_py[idx] = (float)py;
}

// ---------------------------------------------------------------------------
// SGEMM: C[M=8192, 768] = A[M,768] @ W[768,768]^T + bias
// 128x128 tile, BK=8, 256 threads, 8x8 microtile (split 4+4 mapping)
// ---------------------------------------------------------------------------
__global__ void __launch_bounds__(256) sgemm_bias(const float* __restrict__ A,
                                                  const float* __restrict__ W,
                                                  const float* __restrict__ bias,
                                                  float* __restrict__ C) {
    __shared__ float As[8][128];
    __shared__ float Bs[8][128];
    int tid = threadIdx.x;
    int m0 = blockIdx.y * 128, n0 = blockIdx.x * 128;
    int lr = tid >> 1, lk = (tid & 1) * 4;
    const float* Ap = A + (size_t)(m0 + lr) * Dq + lk;
    const float* Wp = W + (size_t)(n0 + lr) * Dq + lk;
    int ty = tid >> 4, tx = tid & 15;
    float acc[8][8] = {};

    for (int k0 = 0; k0 < Dq; k0 += 8) {
        float4 a4 = *(const float4*)(Ap + k0);
        float4 w4 = *(const float4*)(Wp + k0);
        As[lk + 0][lr] = a4.x; As[lk + 1][lr] = a4.y; As[lk + 2][lr] = a4.z; As[lk + 3][lr] = a4.w;
        Bs[lk + 0][lr] = w4.x; Bs[lk + 1][lr] = w4.y; Bs[lk + 2][lr] = w4.z; Bs[lk + 3][lr] = w4.w;
        __syncthreads();
        #pragma unroll
        for (int kk = 0; kk < 8; kk++) {
            float4 a0 = *(const float4*)&As[kk][ty * 4];
            float4 a1 = *(const float4*)&As[kk][64 + ty * 4];
            float4 b0 = *(const float4*)&Bs[kk][tx * 4];
            float4 b1 = *(const float4*)&Bs[kk][64 + tx * 4];
            float a[8]  = {a0.x, a0.y, a0.z, a0.w, a1.x, a1.y, a1.z, a1.w};
            float bb[8] = {b0.x, b0.y, b0.z, b0.w, b1.x, b1.y, b1.z, b1.w};
            #pragma unroll
            for (int i = 0; i < 8; i++)
                #pragma unroll
                for (int j = 0; j < 8; j++)
                    acc[i][j] = fmaf(a[i], bb[j], acc[i][j]);
        }
        __syncthreads();
    }
    #pragma unroll
    for (int i = 0; i < 8; i++) {
        int m = m0 + (i < 4 ? ty * 4 + i : 64 + ty * 4 + i - 4);
        float* cp = C + (size_t)m * Dq + n0;
        #pragma unroll
        for (int j = 0; j < 8; j++) {
            int n = (j < 4 ? tx * 4 + j : 64 + tx * 4 + j - 4);
            cp[n] = acc[i][j] + bias[n0 + n];
        }
    }
}

// ---------------------------------------------------------------------------
// Scores: logits[b,h,q,k] = 0.125*dot(q,k) + dist_emb[bin(b,q,k), h]
// One block computes a 64x64 tile for one (b,h). Writes to att region of d_out.
// ---------------------------------------------------------------------------
__global__ void __launch_bounds__(256) scores_kernel(const float* __restrict__ dist_emb,
                                                     float* __restrict__ att) {
    int bh = blockIdx.z;
    int b = bh / Hq, h = bh - b * Hq;
    int q0 = blockIdx.y * 64, k0 = blockIdx.x * 64;
    __shared__ float Qs[64][65];
    __shared__ float Ks[64][65];
    __shared__ float biastab[201];
    __shared__ float pxq[64], pyq[64], pxk[64], pyk[64];
    int tid = threadIdx.x;

    for (int i = tid; i < 64 * 16; i += 256) {
        int r = i >> 4, c = (i & 15) * 4;
        float4 qv = *(const float4*)(g_q + ((size_t)((b * Nq + q0 + r) * Hq + h)) * DKq + c);
        Qs[r][c] = qv.x; Qs[r][c + 1] = qv.y; Qs[r][c + 2] = qv.z; Qs[r][c + 3] = qv.w;
        float4 kv = *(const float4*)(g_k + ((size_t)((b * Nq + k0 + r) * Hq + h)) * DKq + c);
        Ks[r][c] = kv.x; Ks[r][c + 1] = kv.y; Ks[r][c + 2] = kv.z; Ks[r][c + 3] = kv.w;
    }
    for (int i = tid; i < 201; i += 256)
        biastab[i] = dist_emb[g_btab[i] * Hq + h];
    if (tid < 64) {
        pxq[tid] = g_px[b * Nq + q0 + tid]; pyq[tid] = g_py[b * Nq + q0 + tid];
        pxk[tid] = g_px[b * Nq + k0 + tid]; pyk[tid] = g_py[b * Nq + k0 + tid];
    }
    __syncthreads();

    int ty = tid >> 4, tx = tid & 15;
    float acc[4][4] = {};
    #pragma unroll 8
    for (int kk = 0; kk < 64; kk++) {
        float a[4], bb[4];
        #pragma unroll
        for (int i = 0; i < 4; i++) a[i] = Qs[ty * 4 + i][kk];
        #pragma unroll
        for (int j = 0; j < 4; j++) bb[j] = Ks[tx * 4 + j][kk];
        #pragma unroll
        for (int i = 0; i < 4; i++)
            #pragma unroll
            for (int j = 0; j < 4; j++)
                acc[i][j] = fmaf(a[i], bb[j], acc[i][j]);
    }
    #pragma unroll
    for (int i = 0; i < 4; i++) {
        int q = q0 + ty * 4 + i;
        float pxi = pxq[ty * 4 + i], pyi = pyq[ty * 4 + i];
        #pragma unroll
        for (int j = 0; j < 4; j++) {
            int k = k0 + tx * 4 + j;
            float dx = pxk[tx * 4 + j] - pxi;
            float dy = pyk[tx * 4 + j] - pyi;
            int d2 = (int)(dx * dx + dy * dy);   // exact small integer
            att[(((size_t)bh) * Nq + q) * Nq + k] = acc[i][j] * 0.125f + biastab[d2];
        }
    }
}

// ---------------------------------------------------------------------------
// Row softmax over last dim (512), one block per row, in place.
// ---------------------------------------------------------------------------
__global__ void __launch_bounds__(256) softmax_kernel(float* __restrict__ att) {
    size_t row = blockIdx.x;
    float* p = att + row * Nq;
    int tid = threadIdx.x;
    float a = p[tid], b2 = p[tid + 256];
    __shared__ float red[8];
    __shared__ float bc;

    float m = fmaxf(a, b2);
    #pragma unroll
    for (int o = 16; o > 0; o >>= 1) m = fmaxf(m, __shfl_down_sync(0xffffffffu, m, o));
    if ((tid & 31) == 0) red[tid >> 5] = m;
    __syncthreads();
    if (tid == 0) {
        float mm = red[0];
        #pragma unroll
        for (int i = 1; i < 8; i++) mm = fmaxf(mm, red[i]);
        bc = mm;
    }
    __syncthreads();
    float mx = bc;
    float e1 = expf(a - mx), e2 = expf(b2 - mx);
    float s = e1 + e2;
    #pragma unroll
    for (int o = 16; o > 0; o >>= 1) s += __shfl_down_sync(0xffffffffu, s, o);
    __syncthreads();
    if ((tid & 31) == 0) red[tid >> 5] = s;
    __syncthreads();
    if (tid == 0) {
        float ss = 0.f;
        #pragma unroll
        for (int i = 0; i < 8; i++) ss += red[i];
        bc = ss;
    }
    __syncthreads();
    float inv = 1.0f / bc;
    p[tid] = e1 * inv;
    p[tid + 256] = e2 * inv;
}

// ---------------------------------------------------------------------------
// AV: out[b,q,h,:] = att[b,h,q,:] @ V[b,:,h,:]  -> g_o in (B,N,H,DK) layout
// One block: (bh, 64 q rows), K loop over 512 in tiles of 32.
// ---------------------------------------------------------------------------
__global__ void __launch_bounds__(256) av_kernel(const float* __restrict__ att) {
    int bh = blockIdx.y;
    int b = bh / Hq, h = bh - b * Hq;
    int q0 = blockIdx.x * 64;
    __shared__ float As[64][33];
    __shared__ float Vs[32][65];
    int tid = threadIdx.x;
    int ty = tid >> 4, tx = tid & 15;
    float acc[4][4] = {};

    for (int kb = 0; kb < Nq; kb += 32) {
        for (int i = tid; i < 64 * 8; i += 256) {
            int r = i >> 3, c = (i & 7) * 4;
            float4 v = *(const float4*)(att + (((size_t)bh) * Nq + q0 + r) * Nq + kb + c);
            As[r][c] = v.x; As[r][c + 1] = v.y; As[r][c + 2] = v.z; As[r][c + 3] = v.w;
        }
        for (int i = tid; i < 32 * 16; i += 256) {
            int r = i >> 4, c = (i & 15) * 4;
            float4 v = *(const float4*)(g_v + ((size_t)((b * Nq + kb + r) * Hq + h)) * DKq + c);
            Vs[r][c] = v.x; Vs[r][c + 1] = v.y; Vs[r][c + 2] = v.z; Vs[r][c + 3] = v.w;
        }
        __syncthreads();
        #pragma unroll 8
        for (int kk = 0; kk < 32; kk++) {
            float a[4], bb[4];
            #pragma unroll
            for (int i = 0; i < 4; i++) a[i] = As[ty * 4 + i][kk];
            #pragma unroll
            for (int j = 0; j < 4; j++) bb[j] = Vs[kk][tx * 4 + j];
            #pragma unroll
            for (int i = 0; i < 4; i++)
                #pragma unroll
                for (int j = 0; j < 4; j++)
                    acc[i][j] = fmaf(a[i], bb[j], acc[i][j]);
        }
        __syncthreads();
    }
    #pragma unroll
    for (int i = 0; i < 4; i++) {
        int q = q0 + ty * 4 + i;
        #pragma unroll
        for (int j = 0; j < 4; j++)
            g_o[((size_t)((b * Nq + q) * Hq + h)) * DKq + tx * 4 + j] = acc[i][j];
    }
}

// ---------------------------------------------------------------------------
extern "C" void kernel_launch(void* const* d_in, const int* in_sizes, int n_in,
                              void* d_out, int out_size) {
    const float* features = (const float*)d_in[0];
    const float* boxes    = (const float*)d_in[1];
    const int*   im       = (const int*)d_in[2];
    const float* Wq = (const float*)d_in[3];  const float* bqv = (const float*)d_in[4];
    const float* Wk = (const float*)d_in[5];  const float* bkv = (const float*)d_in[6];
    const float* Wv = (const float*)d_in[7];  const float* bvv = (const float*)d_in[8];
    const float* Wo = (const float*)d_in[9];  const float* bov = (const float*)d_in[10];
    const float* gamma = (const float*)d_in[11];
    const float* beta  = (const float*)d_in[12];
    const float* demb  = (const float*)d_in[13];

    float* out = (float*)d_out;                       // (B,N,D)
    float* att = out + (size_t)TOK * Dq;              // (B,H,N,N)

    void *px_, *pq_, *pk_, *pv_, *po_;
    cudaGetSymbolAddress(&px_, g_x);
    cudaGetSymbolAddress(&pq_, g_q);
    cudaGetSymbolAddress(&pk_, g_k);
    cudaGetSymbolAddress(&pv_, g_v);
    cudaGetSymbolAddress(&po_, g_o);

    ln_kernel<<<TOK, 256>>>(features, gamma, beta);
    bins_kernel<<<(TOK + 255) / 256, 256>>>(boxes, im);

    dim3 gproj(Dq / 128, TOK / 128);   // (6, 64)
    sgemm_bias<<<gproj, 256>>>((const float*)px_, Wq, bqv, (float*)pq_);
    sgemm_bias<<<gproj, 256>>>((const float*)px_, Wk, bkv, (float*)pk_);
    sgemm_bias<<<gproj, 256>>>((const float*)px_, Wv, bvv, (float*)pv_);

    scores_kernel<<<dim3(8, 8, Bq * Hq), 256>>>(demb, att);
    softmax_kernel<<<Bq * Hq * Nq, 256>>>(att);
    av_kernel<<<dim3(8, Bq * Hq), 256>>>(att);

    sgemm_bias<<<gproj, 256>>>((const float*)po_, Wo, bov, out);
}